// round 11
// baseline (speedup 1.0000x reference)
#include <cuda_runtime.h>
#include <cuda_fp16.h>
#include <cstdint>

#define N_NODES 50000
#define N_EDGES 800000
#define IN_F    256
#define OUT_F   64
#define N_PAD   50176      // 1024 * 49, padded node count for the scan
#define SCAN_SMEM (N_PAD * 4)
#define E4 (N_EDGES / 4)   // 200000
#define GEMM_BLOCKS 391    // ceil(50000/128)
#define SBH 264            // sB stride in halves (256 + 8) -> LDSM conflict-free

// Scratch (device globals: allocation-guard compliant, zero-init at load)
__device__ __half g_hw[(size_t)N_NODES * OUT_F];  // projected*norm feats (fp16)
__device__ int    g_deg[N_NODES];                 // in-degree (zeroed by aggregate)
__device__ int    g_start[N_NODES];               // CSR row starts
__device__ int    g_slot[N_EDGES];                // per-edge slot within dst bucket
__device__ int    g_esrc[N_EDGES];                // src ids bucketed by dst

// ---------------------------------------------------------------------------
// Histogram + slot recording (side stream, concurrent with GEMM)
// ---------------------------------------------------------------------------
__global__ __launch_bounds__(256) void hist_kernel(const int4* __restrict__ dst4) {
    const int i = blockIdx.x * 256 + threadIdx.x;
    if (i >= E4) return;
    const int4 d = __ldg(dst4 + i);
    int4 sl;
    sl.x = atomicAdd(&g_deg[d.x], 1);
    sl.y = atomicAdd(&g_deg[d.y], 1);
    sl.z = atomicAdd(&g_deg[d.z], 1);
    sl.w = atomicAdd(&g_deg[d.w], 1);
    ((int4*)g_slot)[i] = sl;
}

// ---------------------------------------------------------------------------
// Single-block exclusive scan of g_deg -> g_start
// ---------------------------------------------------------------------------
__global__ __launch_bounds__(1024) void scan_kernel() {
    extern __shared__ int sh[];          // N_PAD ints
    __shared__ int ssum[1024];
    const int t = threadIdx.x;

    for (int i = t; i < N_PAD; i += 1024)
        sh[i] = (i < N_NODES) ? g_deg[i] : 0;
    __syncthreads();

    const int base = t * 49;
    int s = 0;
#pragma unroll
    for (int i = 0; i < 49; i++) s += sh[base + i];
    ssum[t] = s;
    __syncthreads();

    for (int off = 1; off < 1024; off <<= 1) {
        int x = (t >= off) ? ssum[t - off] : 0;
        __syncthreads();
        ssum[t] += x;
        __syncthreads();
    }

    int run = ssum[t] - s;
#pragma unroll
    for (int i = 0; i < 49; i++) {
        int v = sh[base + i];
        sh[base + i] = run;
        run += v;
    }
    __syncthreads();

    for (int i = t; i < N_NODES; i += 1024)
        g_start[i] = sh[i];
}

// ---------------------------------------------------------------------------
// Atomic-free fill: g_esrc[g_start[dst] + slot] = src   (4 edges per thread)
// ---------------------------------------------------------------------------
__global__ __launch_bounds__(256) void fill_kernel(
    const int4* __restrict__ src4,
    const int4* __restrict__ dst4)
{
    const int i = blockIdx.x * 256 + threadIdx.x;
    if (i >= E4) return;
    const int4 d  = __ldg(dst4 + i);
    const int4 sl = ((const int4*)g_slot)[i];
    const int4 s  = __ldg(src4 + i);
    g_esrc[g_start[d.x] + sl.x] = s.x;
    g_esrc[g_start[d.y] + sl.y] = s.y;
    g_esrc[g_start[d.z] + sl.z] = s.z;
    g_esrc[g_start[d.w] + sl.w] = s.w;
}

// ---------------------------------------------------------------------------
// fp16 GEMM + fold norm, streaming A:  g_hw[n,:] = fp16((h[n,:] @ W) * norm[n])
// Per block: 128 rows x 64 cols.  W staged ONCE to smem (fp16, [n][k] + pad);
// A fragments loaded straight from global (LDG.64 + pack).
// DEPTH-4 register prefetch (was 2): loads issue ~3-4 MMA-steps (~400 cyc)
// before use, covering DRAM latency with per-warp MLP instead of occupancy.
// ---------------------------------------------------------------------------
__global__ __launch_bounds__(256, 2) void gemm_f16_kernel(
    const float* __restrict__ h,
    const float* __restrict__ w,
    const float* __restrict__ norm)
{
    __shared__ alignas(16) __half sB[64 * SBH];

    const int tid  = threadIdx.x;
    const int warp = tid >> 5;
    const int lane = tid & 31;
    const int g    = lane >> 2;
    const int t    = lane & 3;
    const int row0 = blockIdx.x * 128;

    // ---- stage full W once: w[k][n] (f32) -> sB[n][k] (f16)
#pragma unroll
    for (int i = 0; i < 16; i++) {
        const int fid = tid + 256 * i;        // float4 id, 0..4095
        const int k   = fid >> 4;             // 0..255
        const int n0  = (fid & 15) * 4;
        const float4 v = __ldg((const float4*)w + fid);
        sB[(n0 + 0) * SBH + k] = __float2half_rn(v.x);
        sB[(n0 + 1) * SBH + k] = __float2half_rn(v.y);
        sB[(n0 + 2) * SBH + k] = __float2half_rn(v.z);
        sB[(n0 + 3) * SBH + k] = __float2half_rn(v.w);
    }
    __syncthreads();

    // ---- per-lane A row pointers (m16n8k16 fragment layout)
    const int r0 = row0 + warp * 16 + g;      // rows 0-7 of warp tile
    const int r1 = r0 + 8;                    // rows 8-15
    const bool ok0 = (r0 < N_NODES);
    const bool ok1 = (r1 < N_NODES);
    const float* pA0 = h + (size_t)r0 * IN_F + 2 * t;
    const float* pA1 = h + (size_t)r1 * IN_F + 2 * t;

    // ---- B ldmatrix lane addresses (round-8 validated mapping)
    const uint32_t sB_u = (uint32_t)__cvta_generic_to_shared(sB);
    const uint32_t bRow = (uint32_t)((lane >> 4) * 8 + (lane & 7));
    const uint32_t bCol = (uint32_t)(((lane >> 3) & 1) * 8);
    uint32_t bAddr[4];
#pragma unroll
    for (int np = 0; np < 4; np++)
        bAddr[np] = sB_u + ((np * 16 + bRow) * SBH + bCol) * 2;

    float acc[8][4];
#pragma unroll
    for (int i = 0; i < 8; i++)
#pragma unroll
        for (int j = 0; j < 4; j++) acc[i][j] = 0.f;

    const float2 z2 = make_float2(0.f, 0.f);
    float2 fA[4][4];                          // depth-4 prefetch ring

#define LDG_A(buf, s)                                                        \
    do {                                                                     \
        const int kb = (s) * 16;                                             \
        fA[buf][0] = ok0 ? __ldg((const float2*)(pA0 + kb    )) : z2;        \
        fA[buf][1] = ok1 ? __ldg((const float2*)(pA1 + kb    )) : z2;        \
        fA[buf][2] = ok0 ? __ldg((const float2*)(pA0 + kb + 8)) : z2;        \
        fA[buf][3] = ok1 ? __ldg((const float2*)(pA1 + kb + 8)) : z2;        \
    } while (0)

    LDG_A(0, 0);
    LDG_A(1, 1);
    LDG_A(2, 2);
    LDG_A(3, 3);

#pragma unroll
    for (int s = 0; s < 16; s++) {
        const int buf = s & 3;
        uint32_t a[4];
#pragma unroll
        for (int i = 0; i < 4; i++) {
            __half2 hh = __floats2half2_rn(fA[buf][i].x, fA[buf][i].y);
            a[i] = *(uint32_t*)&hh;
        }
        if (s < 12) LDG_A(buf, s + 4);

#pragma unroll
        for (int np = 0; np < 4; np++) {
            uint32_t b0, b1, b2, b3;
            asm volatile(
                "ldmatrix.sync.aligned.m8n8.x4.shared.b16 {%0,%1,%2,%3}, [%4];"
                : "=r"(b0), "=r"(b1), "=r"(b2), "=r"(b3)
                : "r"(bAddr[np] + s * 32));
            asm volatile(
                "mma.sync.aligned.m16n8k16.row.col.f32.f16.f16.f32 "
                "{%0,%1,%2,%3}, {%4,%5,%6,%7}, {%8,%9}, {%0,%1,%2,%3};"
                : "+f"(acc[np * 2][0]), "+f"(acc[np * 2][1]),
                  "+f"(acc[np * 2][2]), "+f"(acc[np * 2][3])
                : "r"(a[0]), "r"(a[1]), "r"(a[2]), "r"(a[3]), "r"(b0), "r"(b1));
            asm volatile(
                "mma.sync.aligned.m16n8k16.row.col.f32.f16.f16.f32 "
                "{%0,%1,%2,%3}, {%4,%5,%6,%7}, {%8,%9}, {%0,%1,%2,%3};"
                : "+f"(acc[np * 2 + 1][0]), "+f"(acc[np * 2 + 1][1]),
                  "+f"(acc[np * 2 + 1][2]), "+f"(acc[np * 2 + 1][3])
                : "r"(a[0]), "r"(a[1]), "r"(a[2]), "r"(a[3]), "r"(b2), "r"(b3));
        }
    }

    // Epilogue: scale by norm[row], convert to fp16, store half2 pairs
    const float nv0 = ok0 ? __ldg(norm + r0) : 0.f;
    const float nv1 = ok1 ? __ldg(norm + r1) : 0.f;
    __half2* __restrict__ hw2 = (__half2*)g_hw;   // 32 half2 per node row
#pragma unroll
    for (int nt = 0; nt < 8; nt++) {
        const int c2 = nt * 4 + t;                // half2 column index
        if (ok0)
            hw2[(size_t)r0 * 32 + c2] =
                __floats2half2_rn(acc[nt][0] * nv0, acc[nt][1] * nv0);
        if (ok1)
            hw2[(size_t)r1 * 32 + c2] =
                __floats2half2_rn(acc[nt][2] * nv1, acc[nt][3] * nv1);
    }
}

// ---------------------------------------------------------------------------
// Aggregate: 4 nodes per warp (two interleaved node-pairs), 16 lanes per node,
// each lane owns 4 halves (8 bytes) of the 128-byte fp16 node row.
// Accumulates in fp32.  Restores g_deg = 0 for the next kernel_launch call.
// ---------------------------------------------------------------------------
__global__ __launch_bounds__(256) void aggregate_kernel(
    const float* __restrict__ norm,
    const float* __restrict__ bias,
    float* __restrict__ out)
{
    const unsigned FULL = 0xFFFFFFFFu;
    const int wid  = (blockIdx.x * 256 + threadIdx.x) >> 5;
    const int base = wid * 4;
    if (base >= N_NODES) return;         // N_NODES % 4 == 0: uniform per warp
    const int lane = threadIdx.x & 31;
    const int half = lane >> 4;          // 0 or 1
    const int fl   = lane & 15;

    int st = 0, dg = 0;
    if (lane < 4) {
        st = g_start[base + lane];
        dg = g_deg[base + lane];
        g_deg[base + lane] = 0;          // restore invariant for next call
    }
    const int stA = __shfl_sync(FULL, st, half);
    const int dgA = __shfl_sync(FULL, dg, half);
    const int stB = __shfl_sync(FULL, st, 2 + half);
    const int dgB = __shfl_sync(FULL, dg, 2 + half);
    const int d0 = __shfl_sync(FULL, dg, 0), d1 = __shfl_sync(FULL, dg, 1);
    const int d2 = __shfl_sync(FULL, dg, 2), d3 = __shfl_sync(FULL, dg, 3);
    const int m = max(max(d0, d1), max(d2, d3));

    const uint2* __restrict__ hwq = (const uint2*)g_hw;  // 16 uint2 per row

    float4 aA = make_float4(0.f, 0.f, 0.f, 0.f);
    float4 aB = make_float4(0.f, 0.f, 0.f, 0.f);

    for (int b = 0; b < m; b += 16) {
        const int iA = (b + fl < dgA) ? __ldg(g_esrc + stA + b + fl) : 0;
        const int iB = (b + fl < dgB) ? __ldg(g_esrc + stB + b + fl) : 0;
#pragma unroll
        for (int j = 0; j < 16; j++) {
            const int sa = __shfl_sync(FULL, iA, (half << 4) + j);
            const int sb = __shfl_sync(FULL, iB, (half << 4) + j);
            if (b + j < dgA) {
                const uint2 v = __ldg(hwq + (size_t)sa * 16 + fl);
                const float2 p0 = __half22float2(*(const __half2*)&v.x);
                const float2 p1 = __half22float2(*(const __half2*)&v.y);
                aA.x += p0.x; aA.y += p0.y; aA.z += p1.x; aA.w += p1.y;
            }
            if (b + j < dgB) {
                const uint2 v = __ldg(hwq + (size_t)sb * 16 + fl);
                const float2 p0 = __half22float2(*(const __half2*)&v.x);
                const float2 p1 = __half22float2(*(const __half2*)&v.y);
                aB.x += p0.x; aB.y += p0.y; aB.z += p1.x; aB.w += p1.y;
            }
        }
    }

    const int nodeA = base + half;
    const int nodeB = base + 2 + half;
    const float nA = __ldg(norm + nodeA);
    const float nB = __ldg(norm + nodeB);
    const float4 bi = ((const float4*)bias)[fl];
    float4 rA, rB;
    rA.x = fmaxf(fmaf(aA.x, nA, bi.x), 0.f);
    rA.y = fmaxf(fmaf(aA.y, nA, bi.y), 0.f);
    rA.z = fmaxf(fmaf(aA.z, nA, bi.z), 0.f);
    rA.w = fmaxf(fmaf(aA.w, nA, bi.w), 0.f);
    rB.x = fmaxf(fmaf(aB.x, nB, bi.x), 0.f);
    rB.y = fmaxf(fmaf(aB.y, nB, bi.y), 0.f);
    rB.z = fmaxf(fmaf(aB.z, nB, bi.z), 0.f);
    rB.w = fmaxf(fmaf(aB.w, nB, bi.w), 0.f);
    ((float4*)out)[(size_t)nodeA * 16 + fl] = rA;
    ((float4*)out)[(size_t)nodeB * 16 + fl] = rB;
}

// ---------------------------------------------------------------------------
extern "C" void kernel_launch(void* const* d_in, const int* in_sizes, int n_in,
                              void* d_out, int out_size)
{
    const float* h      = (const float*)d_in[0];
    const float* norm   = (const float*)d_in[1];
    const int*   src    = (const int*)d_in[2];
    const int*   dst    = (const int*)d_in[3];
    const float* weight = (const float*)d_in[4];
    const float* bias   = (const float*)d_in[5];
    float* out = (float*)d_out;

    static cudaStream_t sB = nullptr;
    static cudaEvent_t  evFork = nullptr, evJoin = nullptr;
    if (sB == nullptr) {
        cudaStreamCreateWithFlags(&sB, cudaStreamNonBlocking);
        cudaEventCreateWithFlags(&evFork, cudaEventDisableTiming);
        cudaEventCreateWithFlags(&evJoin, cudaEventDisableTiming);
        cudaFuncSetAttribute(scan_kernel,
                             cudaFuncAttributeMaxDynamicSharedMemorySize,
                             SCAN_SMEM);
    }

    // Fork: CSR build on side stream, concurrent with the GEMM.
    cudaEventRecord(evFork, 0);
    cudaStreamWaitEvent(sB, evFork, 0);
    hist_kernel<<<(E4 + 255) / 256, 256, 0, sB>>>((const int4*)dst);
    scan_kernel<<<1, 1024, SCAN_SMEM, sB>>>();
    fill_kernel<<<(E4 + 255) / 256, 256, 0, sB>>>((const int4*)src,
                                                  (const int4*)dst);
    cudaEventRecord(evJoin, sB);

    // GEMM on the main stream (concurrent with CSR build).
    gemm_f16_kernel<<<GEMM_BLOCKS, 256>>>(h, weight, norm);

    // Join, then aggregate (+ fused norm/bias/relu epilogue).
    cudaStreamWaitEvent(0, evJoin, 0);
    {
        const int warps  = N_NODES / 4;          // 12500
        const int blocks = (warps * 32 + 255) / 256;
        aggregate_kernel<<<blocks, 256>>>(norm, bias, out);
    }
}

// round 12
// speedup vs baseline: 1.0891x; 1.0891x over previous
#include <cuda_runtime.h>
#include <cuda_fp16.h>
#include <cstdint>

#define N_NODES 50000
#define N_EDGES 800000
#define IN_F    256
#define OUT_F   64
#define N_PAD   50176      // 1024 * 49, padded node count for the scan
#define SCAN_SMEM (N_PAD * 4)
#define E4 (N_EDGES / 4)   // 200000
#define GEMM_BLOCKS 391    // ceil(50000/128)
#define SBH 264            // sB stride in halves (256 + 8) -> LDSM conflict-free

// Scratch (device globals: allocation-guard compliant, zero-init at load)
// g_hw has ONE extra row (index N_NODES) that is never written -> stays zero.
// The aggregate uses it as a branchless sentinel target.
__device__ __half g_hw[(size_t)(N_NODES + 1) * OUT_F];
__device__ int    g_deg[N_NODES];                 // in-degree (zeroed by aggregate)
__device__ int    g_start[N_NODES];               // CSR row starts
__device__ int    g_slot[N_EDGES];                // per-edge slot within dst bucket
__device__ int    g_esrc[N_EDGES];                // src ids bucketed by dst

// ---------------------------------------------------------------------------
// Histogram + slot recording (side stream, concurrent with GEMM)
// ---------------------------------------------------------------------------
__global__ __launch_bounds__(256) void hist_kernel(const int4* __restrict__ dst4) {
    const int i = blockIdx.x * 256 + threadIdx.x;
    if (i >= E4) return;
    const int4 d = __ldg(dst4 + i);
    int4 sl;
    sl.x = atomicAdd(&g_deg[d.x], 1);
    sl.y = atomicAdd(&g_deg[d.y], 1);
    sl.z = atomicAdd(&g_deg[d.z], 1);
    sl.w = atomicAdd(&g_deg[d.w], 1);
    ((int4*)g_slot)[i] = sl;
}

// ---------------------------------------------------------------------------
// Single-block exclusive scan of g_deg -> g_start
// ---------------------------------------------------------------------------
__global__ __launch_bounds__(1024) void scan_kernel() {
    extern __shared__ int sh[];          // N_PAD ints
    __shared__ int ssum[1024];
    const int t = threadIdx.x;

    for (int i = t; i < N_PAD; i += 1024)
        sh[i] = (i < N_NODES) ? g_deg[i] : 0;
    __syncthreads();

    const int base = t * 49;
    int s = 0;
#pragma unroll
    for (int i = 0; i < 49; i++) s += sh[base + i];
    ssum[t] = s;
    __syncthreads();

    for (int off = 1; off < 1024; off <<= 1) {
        int x = (t >= off) ? ssum[t - off] : 0;
        __syncthreads();
        ssum[t] += x;
        __syncthreads();
    }

    int run = ssum[t] - s;
#pragma unroll
    for (int i = 0; i < 49; i++) {
        int v = sh[base + i];
        sh[base + i] = run;
        run += v;
    }
    __syncthreads();

    for (int i = t; i < N_NODES; i += 1024)
        g_start[i] = sh[i];
}

// ---------------------------------------------------------------------------
// Atomic-free fill: g_esrc[g_start[dst] + slot] = src   (4 edges per thread)
// ---------------------------------------------------------------------------
__global__ __launch_bounds__(256) void fill_kernel(
    const int4* __restrict__ src4,
    const int4* __restrict__ dst4)
{
    const int i = blockIdx.x * 256 + threadIdx.x;
    if (i >= E4) return;
    const int4 d  = __ldg(dst4 + i);
    const int4 sl = ((const int4*)g_slot)[i];
    const int4 s  = __ldg(src4 + i);
    g_esrc[g_start[d.x] + sl.x] = s.x;
    g_esrc[g_start[d.y] + sl.y] = s.y;
    g_esrc[g_start[d.z] + sl.z] = s.z;
    g_esrc[g_start[d.w] + sl.w] = s.w;
}

// ---------------------------------------------------------------------------
// fp16 GEMM + fold norm, streaming A (round-10 validated version: depth-2
// register prefetch, no mainloop barriers, occupancy 3 blocks/SM).
// ---------------------------------------------------------------------------
__global__ __launch_bounds__(256, 3) void gemm_f16_kernel(
    const float* __restrict__ h,
    const float* __restrict__ w,
    const float* __restrict__ norm)
{
    __shared__ alignas(16) __half sB[64 * SBH];

    const int tid  = threadIdx.x;
    const int warp = tid >> 5;
    const int lane = tid & 31;
    const int g    = lane >> 2;
    const int t    = lane & 3;
    const int row0 = blockIdx.x * 128;

    // ---- stage full W once: w[k][n] (f32) -> sB[n][k] (f16)
#pragma unroll
    for (int i = 0; i < 16; i++) {
        const int fid = tid + 256 * i;        // float4 id, 0..4095
        const int k   = fid >> 4;             // 0..255
        const int n0  = (fid & 15) * 4;
        const float4 v = __ldg((const float4*)w + fid);
        sB[(n0 + 0) * SBH + k] = __float2half_rn(v.x);
        sB[(n0 + 1) * SBH + k] = __float2half_rn(v.y);
        sB[(n0 + 2) * SBH + k] = __float2half_rn(v.z);
        sB[(n0 + 3) * SBH + k] = __float2half_rn(v.w);
    }
    __syncthreads();

    // ---- per-lane A row pointers (m16n8k16 fragment layout)
    const int r0 = row0 + warp * 16 + g;      // rows 0-7 of warp tile
    const int r1 = r0 + 8;                    // rows 8-15
    const bool ok0 = (r0 < N_NODES);
    const bool ok1 = (r1 < N_NODES);
    const float* pA0 = h + (size_t)r0 * IN_F + 2 * t;
    const float* pA1 = h + (size_t)r1 * IN_F + 2 * t;

    // ---- B ldmatrix lane addresses (round-8 validated mapping)
    const uint32_t sB_u = (uint32_t)__cvta_generic_to_shared(sB);
    const uint32_t bRow = (uint32_t)((lane >> 4) * 8 + (lane & 7));
    const uint32_t bCol = (uint32_t)(((lane >> 3) & 1) * 8);
    uint32_t bAddr[4];
#pragma unroll
    for (int np = 0; np < 4; np++)
        bAddr[np] = sB_u + ((np * 16 + bRow) * SBH + bCol) * 2;

    float acc[8][4];
#pragma unroll
    for (int i = 0; i < 8; i++)
#pragma unroll
        for (int j = 0; j < 4; j++) acc[i][j] = 0.f;

    const float2 z2 = make_float2(0.f, 0.f);
    float2 fA[2][4];

#define LDG_A(buf, s)                                                        \
    do {                                                                     \
        const int kb = (s) * 16;                                             \
        fA[buf][0] = ok0 ? __ldg((const float2*)(pA0 + kb    )) : z2;        \
        fA[buf][1] = ok1 ? __ldg((const float2*)(pA1 + kb    )) : z2;        \
        fA[buf][2] = ok0 ? __ldg((const float2*)(pA0 + kb + 8)) : z2;        \
        fA[buf][3] = ok1 ? __ldg((const float2*)(pA1 + kb + 8)) : z2;        \
    } while (0)

    LDG_A(0, 0);
    LDG_A(1, 1);

#pragma unroll
    for (int s = 0; s < 16; s++) {
        const int buf = s & 1;
        uint32_t a[4];
#pragma unroll
        for (int i = 0; i < 4; i++) {
            __half2 hh = __floats2half2_rn(fA[buf][i].x, fA[buf][i].y);
            a[i] = *(uint32_t*)&hh;
        }
        if (s < 14) LDG_A(buf, s + 2);

#pragma unroll
        for (int np = 0; np < 4; np++) {
            uint32_t b0, b1, b2, b3;
            asm volatile(
                "ldmatrix.sync.aligned.m8n8.x4.shared.b16 {%0,%1,%2,%3}, [%4];"
                : "=r"(b0), "=r"(b1), "=r"(b2), "=r"(b3)
                : "r"(bAddr[np] + s * 32));
            asm volatile(
                "mma.sync.aligned.m16n8k16.row.col.f32.f16.f16.f32 "
                "{%0,%1,%2,%3}, {%4,%5,%6,%7}, {%8,%9}, {%0,%1,%2,%3};"
                : "+f"(acc[np * 2][0]), "+f"(acc[np * 2][1]),
                  "+f"(acc[np * 2][2]), "+f"(acc[np * 2][3])
                : "r"(a[0]), "r"(a[1]), "r"(a[2]), "r"(a[3]), "r"(b0), "r"(b1));
            asm volatile(
                "mma.sync.aligned.m16n8k16.row.col.f32.f16.f16.f32 "
                "{%0,%1,%2,%3}, {%4,%5,%6,%7}, {%8,%9}, {%0,%1,%2,%3};"
                : "+f"(acc[np * 2 + 1][0]), "+f"(acc[np * 2 + 1][1]),
                  "+f"(acc[np * 2 + 1][2]), "+f"(acc[np * 2 + 1][3])
                : "r"(a[0]), "r"(a[1]), "r"(a[2]), "r"(a[3]), "r"(b2), "r"(b3));
        }
    }

    // Epilogue: scale by norm[row], convert to fp16, store half2 pairs
    const float nv0 = ok0 ? __ldg(norm + r0) : 0.f;
    const float nv1 = ok1 ? __ldg(norm + r1) : 0.f;
    __half2* __restrict__ hw2 = (__half2*)g_hw;   // 32 half2 per node row
#pragma unroll
    for (int nt = 0; nt < 8; nt++) {
        const int c2 = nt * 4 + t;                // half2 column index
        if (ok0)
            hw2[(size_t)r0 * 32 + c2] =
                __floats2half2_rn(acc[nt][0] * nv0, acc[nt][1] * nv0);
        if (ok1)
            hw2[(size_t)r1 * 32 + c2] =
                __floats2half2_rn(acc[nt][2] * nv1, acc[nt][3] * nv1);
    }
}

// ---------------------------------------------------------------------------
// Aggregate: 4 nodes per warp, BRANCHLESS inner loop.
// Out-of-range slots gather the zero sentinel row (index N_NODES), so all
// 32 LDG.64s per batch issue unconditionally back-to-back (max MLP, no
// predicate/alu overhead).  Restores g_deg = 0 for the next call.
// ---------------------------------------------------------------------------
__global__ __launch_bounds__(256) void aggregate_kernel(
    const float* __restrict__ norm,
    const float* __restrict__ bias,
    float* __restrict__ out)
{
    const unsigned FULL = 0xFFFFFFFFu;
    const int wid  = (blockIdx.x * 256 + threadIdx.x) >> 5;
    const int base = wid * 4;
    if (base >= N_NODES) return;         // N_NODES % 4 == 0: uniform per warp
    const int lane = threadIdx.x & 31;
    const int half = lane >> 4;          // 0 or 1
    const int fl   = lane & 15;

    int st = 0, dg = 0;
    if (lane < 4) {
        st = g_start[base + lane];
        dg = g_deg[base + lane];
        g_deg[base + lane] = 0;          // restore invariant for next call
    }
    const int stA = __shfl_sync(FULL, st, half);
    const int dgA = __shfl_sync(FULL, dg, half);
    const int stB = __shfl_sync(FULL, st, 2 + half);
    const int dgB = __shfl_sync(FULL, dg, 2 + half);
    const int d0 = __shfl_sync(FULL, dg, 0), d1 = __shfl_sync(FULL, dg, 1);
    const int d2 = __shfl_sync(FULL, dg, 2), d3 = __shfl_sync(FULL, dg, 3);
    const int m = max(max(d0, d1), max(d2, d3));

    const uint2* __restrict__ hwq = (const uint2*)g_hw;  // 16 uint2 per row

    float4 aA = make_float4(0.f, 0.f, 0.f, 0.f);
    float4 aB = make_float4(0.f, 0.f, 0.f, 0.f);

    for (int b = 0; b < m; b += 16) {
        // Sentinel N_NODES for out-of-range slots -> zero row, adds 0.
        const int iA = (b + fl < dgA) ? __ldg(g_esrc + stA + b + fl) : N_NODES;
        const int iB = (b + fl < dgB) ? __ldg(g_esrc + stB + b + fl) : N_NODES;
#pragma unroll
        for (int j = 0; j < 16; j++) {
            const int sa = __shfl_sync(FULL, iA, (half << 4) + j);
            const int sb = __shfl_sync(FULL, iB, (half << 4) + j);
            const uint2 vA = __ldg(hwq + (size_t)sa * 16 + fl);
            const uint2 vB = __ldg(hwq + (size_t)sb * 16 + fl);
            const float2 a0 = __half22float2(*(const __half2*)&vA.x);
            const float2 a1 = __half22float2(*(const __half2*)&vA.y);
            const float2 b0 = __half22float2(*(const __half2*)&vB.x);
            const float2 b1 = __half22float2(*(const __half2*)&vB.y);
            aA.x += a0.x; aA.y += a0.y; aA.z += a1.x; aA.w += a1.y;
            aB.x += b0.x; aB.y += b0.y; aB.z += b1.x; aB.w += b1.y;
        }
    }

    const int nodeA = base + half;
    const int nodeB = base + 2 + half;
    const float nA = __ldg(norm + nodeA);
    const float nB = __ldg(norm + nodeB);
    const float4 bi = ((const float4*)bias)[fl];
    float4 rA, rB;
    rA.x = fmaxf(fmaf(aA.x, nA, bi.x), 0.f);
    rA.y = fmaxf(fmaf(aA.y, nA, bi.y), 0.f);
    rA.z = fmaxf(fmaf(aA.z, nA, bi.z), 0.f);
    rA.w = fmaxf(fmaf(aA.w, nA, bi.w), 0.f);
    rB.x = fmaxf(fmaf(aB.x, nB, bi.x), 0.f);
    rB.y = fmaxf(fmaf(aB.y, nB, bi.y), 0.f);
    rB.z = fmaxf(fmaf(aB.z, nB, bi.z), 0.f);
    rB.w = fmaxf(fmaf(aB.w, nB, bi.w), 0.f);
    ((float4*)out)[(size_t)nodeA * 16 + fl] = rA;
    ((float4*)out)[(size_t)nodeB * 16 + fl] = rB;
}

// ---------------------------------------------------------------------------
extern "C" void kernel_launch(void* const* d_in, const int* in_sizes, int n_in,
                              void* d_out, int out_size)
{
    const float* h      = (const float*)d_in[0];
    const float* norm   = (const float*)d_in[1];
    const int*   src    = (const int*)d_in[2];
    const int*   dst    = (const int*)d_in[3];
    const float* weight = (const float*)d_in[4];
    const float* bias   = (const float*)d_in[5];
    float* out = (float*)d_out;

    static cudaStream_t sB = nullptr;
    static cudaEvent_t  evFork = nullptr, evJoin = nullptr;
    if (sB == nullptr) {
        cudaStreamCreateWithFlags(&sB, cudaStreamNonBlocking);
        cudaEventCreateWithFlags(&evFork, cudaEventDisableTiming);
        cudaEventCreateWithFlags(&evJoin, cudaEventDisableTiming);
        cudaFuncSetAttribute(scan_kernel,
                             cudaFuncAttributeMaxDynamicSharedMemorySize,
                             SCAN_SMEM);
    }

    // Fork: CSR build on side stream, concurrent with the GEMM.
    cudaEventRecord(evFork, 0);
    cudaStreamWaitEvent(sB, evFork, 0);
    hist_kernel<<<(E4 + 255) / 256, 256, 0, sB>>>((const int4*)dst);
    scan_kernel<<<1, 1024, SCAN_SMEM, sB>>>();
    fill_kernel<<<(E4 + 255) / 256, 256, 0, sB>>>((const int4*)src,
                                                  (const int4*)dst);
    cudaEventRecord(evJoin, sB);

    // GEMM on the main stream (concurrent with CSR build).
    gemm_f16_kernel<<<GEMM_BLOCKS, 256>>>(h, weight, norm);

    // Join, then aggregate (+ fused norm/bias/relu epilogue).
    cudaStreamWaitEvent(0, evJoin, 0);
    {
        const int warps  = N_NODES / 4;          // 12500
        const int blocks = (warps * 32 + 255) / 256;
        aggregate_kernel<<<blocks, 256>>>(norm, bias, out);
    }
}

// round 13
// speedup vs baseline: 1.1341x; 1.0414x over previous
#include <cuda_runtime.h>
#include <cuda_fp16.h>
#include <cstdint>

#define N_NODES 50000
#define N_EDGES 800000
#define IN_F    256
#define OUT_F   64
#define N_PAD   50176      // 1024 * 49, padded node count for the scan
#define SCAN_SMEM (N_PAD * 4)
#define E4 (N_EDGES / 4)   // 200000
#define GEMM_BLOCKS 391    // ceil(50000/128)
#define SBH 264            // sB stride in halves (256 + 8) -> LDSM conflict-free
#define AWS 24             // per-warp A slab row stride in halves (16+8 pad)

// Scratch (device globals: allocation-guard compliant, zero-init at load)
__device__ __half g_hw[(size_t)N_NODES * OUT_F];  // projected*norm feats (fp16)
__device__ int    g_deg[N_NODES];                 // in-degree (zeroed by aggregate)
__device__ int    g_start[N_NODES];               // CSR row starts
__device__ int    g_slot[N_EDGES];                // per-edge slot within dst bucket
__device__ int    g_esrc[N_EDGES];                // src ids bucketed by dst

// ---------------------------------------------------------------------------
// Histogram + slot recording (side stream, concurrent with GEMM)
// ---------------------------------------------------------------------------
__global__ __launch_bounds__(256) void hist_kernel(const int4* __restrict__ dst4) {
    const int i = blockIdx.x * 256 + threadIdx.x;
    if (i >= E4) return;
    const int4 d = __ldg(dst4 + i);
    int4 sl;
    sl.x = atomicAdd(&g_deg[d.x], 1);
    sl.y = atomicAdd(&g_deg[d.y], 1);
    sl.z = atomicAdd(&g_deg[d.z], 1);
    sl.w = atomicAdd(&g_deg[d.w], 1);
    ((int4*)g_slot)[i] = sl;
}

// ---------------------------------------------------------------------------
// Single-block exclusive scan of g_deg -> g_start
// ---------------------------------------------------------------------------
__global__ __launch_bounds__(1024) void scan_kernel() {
    extern __shared__ int sh[];          // N_PAD ints
    __shared__ int ssum[1024];
    const int t = threadIdx.x;

    for (int i = t; i < N_PAD; i += 1024)
        sh[i] = (i < N_NODES) ? g_deg[i] : 0;
    __syncthreads();

    const int base = t * 49;
    int s = 0;
#pragma unroll
    for (int i = 0; i < 49; i++) s += sh[base + i];
    ssum[t] = s;
    __syncthreads();

    for (int off = 1; off < 1024; off <<= 1) {
        int x = (t >= off) ? ssum[t - off] : 0;
        __syncthreads();
        ssum[t] += x;
        __syncthreads();
    }

    int run = ssum[t] - s;
#pragma unroll
    for (int i = 0; i < 49; i++) {
        int v = sh[base + i];
        sh[base + i] = run;
        run += v;
    }
    __syncthreads();

    for (int i = t; i < N_NODES; i += 1024)
        g_start[i] = sh[i];
}

// ---------------------------------------------------------------------------
// Atomic-free fill: g_esrc[g_start[dst] + slot] = src   (4 edges per thread)
// ---------------------------------------------------------------------------
__global__ __launch_bounds__(256) void fill_kernel(
    const int4* __restrict__ src4,
    const int4* __restrict__ dst4)
{
    const int i = blockIdx.x * 256 + threadIdx.x;
    if (i >= E4) return;
    const int4 d  = __ldg(dst4 + i);
    const int4 sl = ((const int4*)g_slot)[i];
    const int4 s  = __ldg(src4 + i);
    g_esrc[g_start[d.x] + sl.x] = s.x;
    g_esrc[g_start[d.y] + sl.y] = s.y;
    g_esrc[g_start[d.z] + sl.z] = s.z;
    g_esrc[g_start[d.w] + sl.w] = s.w;
}

// ---------------------------------------------------------------------------
// fp16 GEMM + fold norm:  g_hw[n,:] = fp16((h[n,:] @ W) * norm[n])
// A loaded with LDG.128 (2 loads/step -> 16 L1 wavefronts, half of LDG.64
// scheme), restaged through a PER-WARP smem slab (double-buffered, private,
// __syncwarp only) and consumed via the round-8-validated ldmatrix mapping.
// W staged once to smem (fp16, [n][k] + pad), depth-2 LDG ring, no block
// barriers in the mainloop.
// ---------------------------------------------------------------------------
__global__ __launch_bounds__(256, 3) void gemm_f16_kernel(
    const float* __restrict__ h,
    const float* __restrict__ w,
    const float* __restrict__ norm)
{
    __shared__ alignas(16) __half sB[64 * SBH];
    __shared__ alignas(16) __half sAw[8][2][16 * AWS];  // warp x stage x slab

    const int tid  = threadIdx.x;
    const int warp = tid >> 5;
    const int lane = tid & 31;
    const int g    = lane >> 2;
    const int t    = lane & 3;
    const int row0 = blockIdx.x * 128;

    // ---- stage full W once: w[k][n] (f32) -> sB[n][k] (f16)
#pragma unroll
    for (int i = 0; i < 16; i++) {
        const int fid = tid + 256 * i;        // float4 id, 0..4095
        const int k   = fid >> 4;             // 0..255
        const int n0  = (fid & 15) * 4;
        const float4 v = __ldg((const float4*)w + fid);
        sB[(n0 + 0) * SBH + k] = __float2half_rn(v.x);
        sB[(n0 + 1) * SBH + k] = __float2half_rn(v.y);
        sB[(n0 + 2) * SBH + k] = __float2half_rn(v.z);
        sB[(n0 + 3) * SBH + k] = __float2half_rn(v.w);
    }
    __syncthreads();

    // ---- per-lane A row pointers: lane (g,t) owns float4 k[4t..4t+3] of
    //      rows r0 = warp*16+g and r1 = r0+8.
    const int r0 = row0 + warp * 16 + g;
    const int r1 = r0 + 8;
    const bool ok0 = (r0 < N_NODES);
    const bool ok1 = (r1 < N_NODES);
    const float* pA0 = h + (size_t)r0 * IN_F + 4 * t;
    const float* pA1 = h + (size_t)r1 * IN_F + 4 * t;

    // ---- A ldmatrix lane address within this warp's slab (R8-validated form)
    const uint32_t rowp = (uint32_t)(((lane >> 3) & 1) * 8 + (lane & 7));
    const uint32_t acol = (uint32_t)((lane >> 4) * 8);
    uint32_t aSlab[2];
#pragma unroll
    for (int st = 0; st < 2; st++)
        aSlab[st] = (uint32_t)__cvta_generic_to_shared(&sAw[warp][st][0]) +
                    (rowp * AWS + acol) * 2;

    // ---- B ldmatrix lane addresses (round-8 validated mapping)
    const uint32_t sB_u = (uint32_t)__cvta_generic_to_shared(sB);
    const uint32_t bRow = (uint32_t)((lane >> 4) * 8 + (lane & 7));
    const uint32_t bCol = (uint32_t)(((lane >> 3) & 1) * 8);
    uint32_t bAddr[4];
#pragma unroll
    for (int np = 0; np < 4; np++)
        bAddr[np] = sB_u + ((np * 16 + bRow) * SBH + bCol) * 2;

    float acc[8][4];
#pragma unroll
    for (int i = 0; i < 8; i++)
#pragma unroll
        for (int j = 0; j < 4; j++) acc[i][j] = 0.f;

    const float4 z4 = make_float4(0.f, 0.f, 0.f, 0.f);
    float4 fR[2][2];                          // depth-2 ring, 2 rows each

#define LDG_A(buf, s)                                                        \
    do {                                                                     \
        const int kb = (s) * 16;                                             \
        fR[buf][0] = ok0 ? __ldg((const float4*)(pA0 + kb)) : z4;            \
        fR[buf][1] = ok1 ? __ldg((const float4*)(pA1 + kb)) : z4;            \
    } while (0)

    LDG_A(0, 0);
    LDG_A(1, 1);

#pragma unroll
    for (int s = 0; s < 16; s++) {
        const int buf = s & 1;
        // convert + store this step's fragment into the warp-private slab
        {
            __half2 p0 = __floats2half2_rn(fR[buf][0].x, fR[buf][0].y);
            __half2 p1 = __floats2half2_rn(fR[buf][0].z, fR[buf][0].w);
            __half2 q0 = __floats2half2_rn(fR[buf][1].x, fR[buf][1].y);
            __half2 q1 = __floats2half2_rn(fR[buf][1].z, fR[buf][1].w);
            uint2 u0, u1;
            u0.x = *(uint32_t*)&p0; u0.y = *(uint32_t*)&p1;
            u1.x = *(uint32_t*)&q0; u1.y = *(uint32_t*)&q1;
            *(uint2*)(&sAw[warp][buf][(g    ) * AWS + 4 * t]) = u0;
            *(uint2*)(&sAw[warp][buf][(g + 8) * AWS + 4 * t]) = u1;
        }
        if (s < 14) LDG_A(buf, s + 2);
        __syncwarp();

        uint32_t a0, a1, a2, a3;
        asm volatile(
            "ldmatrix.sync.aligned.m8n8.x4.shared.b16 {%0,%1,%2,%3}, [%4];"
            : "=r"(a0), "=r"(a1), "=r"(a2), "=r"(a3)
            : "r"(aSlab[buf]));

#pragma unroll
        for (int np = 0; np < 4; np++) {
            uint32_t b0, b1, b2, b3;
            asm volatile(
                "ldmatrix.sync.aligned.m8n8.x4.shared.b16 {%0,%1,%2,%3}, [%4];"
                : "=r"(b0), "=r"(b1), "=r"(b2), "=r"(b3)
                : "r"(bAddr[np] + s * 32));
            asm volatile(
                "mma.sync.aligned.m16n8k16.row.col.f32.f16.f16.f32 "
                "{%0,%1,%2,%3}, {%4,%5,%6,%7}, {%8,%9}, {%0,%1,%2,%3};"
                : "+f"(acc[np * 2][0]), "+f"(acc[np * 2][1]),
                  "+f"(acc[np * 2][2]), "+f"(acc[np * 2][3])
                : "r"(a0), "r"(a1), "r"(a2), "r"(a3), "r"(b0), "r"(b1));
            asm volatile(
                "mma.sync.aligned.m16n8k16.row.col.f32.f16.f16.f32 "
                "{%0,%1,%2,%3}, {%4,%5,%6,%7}, {%8,%9}, {%0,%1,%2,%3};"
                : "+f"(acc[np * 2 + 1][0]), "+f"(acc[np * 2 + 1][1]),
                  "+f"(acc[np * 2 + 1][2]), "+f"(acc[np * 2 + 1][3])
                : "r"(a0), "r"(a1), "r"(a2), "r"(a3), "r"(b2), "r"(b3));
        }
        __syncwarp();   // all lanes done reading slab[buf] before next refill
    }

    // Epilogue: scale by norm[row], convert to fp16, store half2 pairs
    const float nv0 = ok0 ? __ldg(norm + r0) : 0.f;
    const float nv1 = ok1 ? __ldg(norm + r1) : 0.f;
    __half2* __restrict__ hw2 = (__half2*)g_hw;   // 32 half2 per node row
#pragma unroll
    for (int nt = 0; nt < 8; nt++) {
        const int c2 = nt * 4 + t;                // half2 column index
        if (ok0)
            hw2[(size_t)r0 * 32 + c2] =
                __floats2half2_rn(acc[nt][0] * nv0, acc[nt][1] * nv0);
        if (ok1)
            hw2[(size_t)r1 * 32 + c2] =
                __floats2half2_rn(acc[nt][2] * nv1, acc[nt][3] * nv1);
    }
}

// ---------------------------------------------------------------------------
// Aggregate (round-10 validated version): 4 nodes per warp, 16 lanes per
// node, each lane owns 8 bytes of the 128-byte fp16 node row; fp32 accum.
// Restores g_deg = 0 for the next kernel_launch call.
// ---------------------------------------------------------------------------
__global__ __launch_bounds__(256) void aggregate_kernel(
    const float* __restrict__ norm,
    const float* __restrict__ bias,
    float* __restrict__ out)
{
    const unsigned FULL = 0xFFFFFFFFu;
    const int wid  = (blockIdx.x * 256 + threadIdx.x) >> 5;
    const int base = wid * 4;
    if (base >= N_NODES) return;         // N_NODES % 4 == 0: uniform per warp
    const int lane = threadIdx.x & 31;
    const int half = lane >> 4;          // 0 or 1
    const int fl   = lane & 15;

    int st = 0, dg = 0;
    if (lane < 4) {
        st = g_start[base + lane];
        dg = g_deg[base + lane];
        g_deg[base + lane] = 0;          // restore invariant for next call
    }
    const int stA = __shfl_sync(FULL, st, half);
    const int dgA = __shfl_sync(FULL, dg, half);
    const int stB = __shfl_sync(FULL, st, 2 + half);
    const int dgB = __shfl_sync(FULL, dg, 2 + half);
    const int d0 = __shfl_sync(FULL, dg, 0), d1 = __shfl_sync(FULL, dg, 1);
    const int d2 = __shfl_sync(FULL, dg, 2), d3 = __shfl_sync(FULL, dg, 3);
    const int m = max(max(d0, d1), max(d2, d3));

    const uint2* __restrict__ hwq = (const uint2*)g_hw;  // 16 uint2 per row

    float4 aA = make_float4(0.f, 0.f, 0.f, 0.f);
    float4 aB = make_float4(0.f, 0.f, 0.f, 0.f);

    for (int b = 0; b < m; b += 16) {
        const int iA = (b + fl < dgA) ? __ldg(g_esrc + stA + b + fl) : 0;
        const int iB = (b + fl < dgB) ? __ldg(g_esrc + stB + b + fl) : 0;
#pragma unroll
        for (int j = 0; j < 16; j++) {
            const int sa = __shfl_sync(FULL, iA, (half << 4) + j);
            const int sb = __shfl_sync(FULL, iB, (half << 4) + j);
            if (b + j < dgA) {
                const uint2 v = __ldg(hwq + (size_t)sa * 16 + fl);
                const float2 p0 = __half22float2(*(const __half2*)&v.x);
                const float2 p1 = __half22float2(*(const __half2*)&v.y);
                aA.x += p0.x; aA.y += p0.y; aA.z += p1.x; aA.w += p1.y;
            }
            if (b + j < dgB) {
                const uint2 v = __ldg(hwq + (size_t)sb * 16 + fl);
                const float2 p0 = __half22float2(*(const __half2*)&v.x);
                const float2 p1 = __half22float2(*(const __half2*)&v.y);
                aB.x += p0.x; aB.y += p0.y; aB.z += p1.x; aB.w += p1.y;
            }
        }
    }

    const int nodeA = base + half;
    const int nodeB = base + 2 + half;
    const float nA = __ldg(norm + nodeA);
    const float nB = __ldg(norm + nodeB);
    const float4 bi = ((const float4*)bias)[fl];
    float4 rA, rB;
    rA.x = fmaxf(fmaf(aA.x, nA, bi.x), 0.f);
    rA.y = fmaxf(fmaf(aA.y, nA, bi.y), 0.f);
    rA.z = fmaxf(fmaf(aA.z, nA, bi.z), 0.f);
    rA.w = fmaxf(fmaf(aA.w, nA, bi.w), 0.f);
    rB.x = fmaxf(fmaf(aB.x, nB, bi.x), 0.f);
    rB.y = fmaxf(fmaf(aB.y, nB, bi.y), 0.f);
    rB.z = fmaxf(fmaf(aB.z, nB, bi.z), 0.f);
    rB.w = fmaxf(fmaf(aB.w, nB, bi.w), 0.f);
    ((float4*)out)[(size_t)nodeA * 16 + fl] = rA;
    ((float4*)out)[(size_t)nodeB * 16 + fl] = rB;
}

// ---------------------------------------------------------------------------
extern "C" void kernel_launch(void* const* d_in, const int* in_sizes, int n_in,
                              void* d_out, int out_size)
{
    const float* h      = (const float*)d_in[0];
    const float* norm   = (const float*)d_in[1];
    const int*   src    = (const int*)d_in[2];
    const int*   dst    = (const int*)d_in[3];
    const float* weight = (const float*)d_in[4];
    const float* bias   = (const float*)d_in[5];
    float* out = (float*)d_out;

    static cudaStream_t sB = nullptr;
    static cudaEvent_t  evFork = nullptr, evJoin = nullptr;
    if (sB == nullptr) {
        cudaStreamCreateWithFlags(&sB, cudaStreamNonBlocking);
        cudaEventCreateWithFlags(&evFork, cudaEventDisableTiming);
        cudaEventCreateWithFlags(&evJoin, cudaEventDisableTiming);
        cudaFuncSetAttribute(scan_kernel,
                             cudaFuncAttributeMaxDynamicSharedMemorySize,
                             SCAN_SMEM);
    }

    // Fork: CSR build on side stream, concurrent with the GEMM.
    cudaEventRecord(evFork, 0);
    cudaStreamWaitEvent(sB, evFork, 0);
    hist_kernel<<<(E4 + 255) / 256, 256, 0, sB>>>((const int4*)dst);
    scan_kernel<<<1, 1024, SCAN_SMEM, sB>>>();
    fill_kernel<<<(E4 + 255) / 256, 256, 0, sB>>>((const int4*)src,
                                                  (const int4*)dst);
    cudaEventRecord(evJoin, sB);

    // GEMM on the main stream (concurrent with CSR build).
    gemm_f16_kernel<<<GEMM_BLOCKS, 256>>>(h, weight, norm);

    // Join, then aggregate (+ fused norm/bias/relu epilogue).
    cudaStreamWaitEvent(0, evJoin, 0);
    {
        const int warps  = N_NODES / 4;          // 12500
        const int blocks = (warps * 32 + 255) / 256;
        aggregate_kernel<<<blocks, 256>>>(norm, bias, out);
    }
}